// round 1
// baseline (speedup 1.0000x reference)
#include <cuda_runtime.h>
#include <math.h>

#define N_NODES  50000
#define N_EDGES  800000
#define ET       (N_EDGES + N_NODES)   // edges + self loops
#define HC       128
#define NHEAD    8
#define NEG_SLOPE 0.2f
#define LN_EPS   1e-5f

// ---------------- scratch (device globals: no cudaMalloc allowed) ------------
__device__ float g_h  [(size_t)N_NODES * HC];     // 25.6 MB  x@W per-head features
__device__ float g_as [(size_t)N_NODES * NHEAD];  // attention logits (src part)
__device__ float g_ad [(size_t)N_NODES * NHEAD];  // attention logits (dst part)
__device__ float g_e  [(size_t)ET * NHEAD];       // 27.2 MB  per-edge exp(logit)
__device__ int   g_deg[N_NODES];
__device__ int   g_off[N_NODES];
__device__ int   g_cur[N_NODES];
__device__ int   g_eid[ET];                       // CSR by destination
__device__ float g_agg[(size_t)N_NODES * HC];     // aggregated output pre-LN

// ---------------- packed f32x2 FMA helpers (sm_100+) -------------------------
__device__ __forceinline__ unsigned long long pack2(float x, float y) {
    unsigned long long r;
    asm("mov.b64 %0, {%1, %2};" : "=l"(r) : "f"(x), "f"(y));
    return r;
}
__device__ __forceinline__ void unpack2(unsigned long long v, float& x, float& y) {
    asm("mov.b64 {%0, %1}, %2;" : "=f"(x), "=f"(y) : "l"(v));
}
__device__ __forceinline__ void fma2(unsigned long long& acc,
                                     unsigned long long a, unsigned long long b) {
    asm("fma.rn.f32x2 %0, %1, %2, %0;" : "+l"(acc) : "l"(a), "l"(b));
}

// ---------------- kernel 0: init ---------------------------------------------
__global__ void init_kernel() {
    int i = blockIdx.x * blockDim.x + threadIdx.x;
    if (i < N_NODES) g_deg[i] = 0;
}

// ---------------- kernel 1: h = x@W, a_s, a_d --------------------------------
// 256 nodes per block, 256 threads (1 node/thread). x tile + W in SMEM.
#define G1_SMEM (256*129*4 + 128*128*4 + 2*128*4)
__global__ void gemm1_kernel(const float* __restrict__ x,
                             const float* __restrict__ W,
                             const float* __restrict__ att_src,
                             const float* __restrict__ att_dst) {
    extern __shared__ float sm[];
    float* xs   = sm;                    // 256 rows, stride 129 (conflict-free)
    float* Ws   = sm + 256*129;          // 128x128
    float* as_s = Ws + 128*128;          // 128
    float* ad_s = as_s + 128;            // 128

    const int t = threadIdx.x;
    const int node0 = blockIdx.x * 256;

    for (int i = t; i < 128*128/4; i += 256)
        ((float4*)Ws)[i] = ((const float4*)W)[i];
    if (t < 128) { as_s[t] = att_src[t]; ad_s[t] = att_dst[t]; }

    for (int i = t; i < 256*32; i += 256) {
        int r = i >> 5, cq = i & 31;
        float4 v = make_float4(0.f, 0.f, 0.f, 0.f);
        if (node0 + r < N_NODES)
            v = ((const float4*)x)[(size_t)(node0 + r) * 32 + cq];
        float* d = &xs[r*129 + cq*4];
        d[0] = v.x; d[1] = v.y; d[2] = v.z; d[3] = v.w;
    }
    __syncthreads();

    const int node = node0 + t;
    if (node >= N_NODES) return;
    const float* xr = &xs[t*129];

    float as_acc[NHEAD] = {0,0,0,0,0,0,0,0};
    float ad_acc[NHEAD] = {0,0,0,0,0,0,0,0};

    for (int g = 0; g < 16; g++) {           // 16 groups of 8 output channels
        unsigned long long a0 = 0ull, a1 = 0ull, a2 = 0ull, a3 = 0ull;
        #pragma unroll 8
        for (int k = 0; k < 128; k++) {
            float xv = xr[k];
            unsigned long long xx = pack2(xv, xv);
            ulonglong2 w0 = *(const ulonglong2*)&Ws[k*128 + (g<<3)];
            ulonglong2 w1 = *(const ulonglong2*)&Ws[k*128 + (g<<3) + 4];
            fma2(a0, xx, w0.x); fma2(a1, xx, w0.y);
            fma2(a2, xx, w1.x); fma2(a3, xx, w1.y);
        }
        float acc[8];
        unpack2(a0, acc[0], acc[1]); unpack2(a1, acc[2], acc[3]);
        unpack2(a2, acc[4], acc[5]); unpack2(a3, acc[6], acc[7]);

        float* hdst = &g_h[(size_t)node * HC + (g<<3)];
        *(float4*)&hdst[0] = make_float4(acc[0], acc[1], acc[2], acc[3]);
        *(float4*)&hdst[4] = make_float4(acc[4], acc[5], acc[6], acc[7]);

        const int head = g >> 1, base = (g & 1) * 8;
        #pragma unroll
        for (int j = 0; j < 8; j++) {
            as_acc[head] += acc[j] * as_s[head*16 + base + j];
            ad_acc[head] += acc[j] * ad_s[head*16 + base + j];
        }
    }
    #pragma unroll
    for (int h = 0; h < NHEAD; h++) {
        g_as[(size_t)node*NHEAD + h] = as_acc[h];
        g_ad[(size_t)node*NHEAD + h] = ad_acc[h];
    }
}

// ---------------- kernel 2: per-edge exp(leaky(logit)) + degree histogram ----
// Segment max is omitted: logits are O(10), exp() is safely in fp32 range, and
// exp(e)/sum(exp(e)) == exp(e-m)/sum(exp(e-m)) mathematically.
__global__ void edge_exp_kernel(const int* __restrict__ ei) {
    int i = blockIdx.x * blockDim.x + threadIdx.x;
    if (i >= ET) return;
    int s, d;
    if (i < N_EDGES) { s = ei[i]; d = ei[N_EDGES + i]; }
    else             { s = d = i - N_EDGES; }

    float4 a0 = *(const float4*)&g_as[(size_t)s*NHEAD];
    float4 a1 = *(const float4*)&g_as[(size_t)s*NHEAD + 4];
    float4 b0 = *(const float4*)&g_ad[(size_t)d*NHEAD];
    float4 b1 = *(const float4*)&g_ad[(size_t)d*NHEAD + 4];

    float e[8] = { a0.x+b0.x, a0.y+b0.y, a0.z+b0.z, a0.w+b0.w,
                   a1.x+b1.x, a1.y+b1.y, a1.z+b1.z, a1.w+b1.w };
    #pragma unroll
    for (int h = 0; h < 8; h++) {
        float v = e[h] > 0.f ? e[h] : NEG_SLOPE * e[h];
        e[h] = expf(v);
    }
    float* dst = &g_e[(size_t)i * NHEAD];
    *(float4*)&dst[0] = make_float4(e[0], e[1], e[2], e[3]);
    *(float4*)&dst[4] = make_float4(e[4], e[5], e[6], e[7]);

    atomicAdd(&g_deg[d], 1);
}

// ---------------- kernel 3: one-block exclusive scan of degrees --------------
__global__ void scan_kernel() {
    __shared__ int buf[1024];
    __shared__ int carry;
    const int t = threadIdx.x;
    if (t == 0) carry = 0;
    __syncthreads();
    for (int base = 0; base < N_NODES; base += 1024) {
        int i = base + t;
        int v = (i < N_NODES) ? g_deg[i] : 0;
        buf[t] = v;
        __syncthreads();
        for (int o = 1; o < 1024; o <<= 1) {
            int add = (t >= o) ? buf[t - o] : 0;
            __syncthreads();
            buf[t] += add;
            __syncthreads();
        }
        int incl = buf[t];
        if (i < N_NODES) {
            int off = carry + incl - v;
            g_off[i] = off;
            g_cur[i] = off;
        }
        __syncthreads();
        if (t == 1023) carry += incl;
        __syncthreads();
    }
}

// ---------------- kernel 4: CSR fill ------------------------------------------
__global__ void csr_fill_kernel(const int* __restrict__ ei) {
    int i = blockIdx.x * blockDim.x + threadIdx.x;
    if (i >= ET) return;
    int d = (i < N_EDGES) ? ei[N_EDGES + i] : (i - N_EDGES);
    int pos = atomicAdd(&g_cur[d], 1);
    g_eid[pos] = i;
}

// ---------------- kernel 5: warp-per-node aggregation -------------------------
// lane -> channels [lane*4, lane*4+4); head = lane>>2.
__global__ void agg_kernel(const int* __restrict__ ei) {
    int wid  = (blockIdx.x * blockDim.x + threadIdx.x) >> 5;
    int lane = threadIdx.x & 31;
    if (wid >= N_NODES) return;
    const int n  = wid;
    const int hd = lane >> 2;
    const int start = g_off[n];
    const int end   = start + g_deg[n];

    // pass 1: per-head softmax denominator
    float dsum = 0.f;
    for (int e = start; e < end; e++) {
        int eid = g_eid[e];
        dsum += g_e[(size_t)eid * NHEAD + hd];
    }
    const float dinv = 1.0f / dsum;

    // pass 2: weighted gather of h[src]
    float ax = 0.f, ay = 0.f, az = 0.f, aw = 0.f;
    for (int e = start; e < end; e++) {
        int eid = g_eid[e];
        int s = (eid < N_EDGES) ? ei[eid] : (eid - N_EDGES);
        float alpha = g_e[(size_t)eid * NHEAD + hd] * dinv;
        float4 hv = *(const float4*)&g_h[(size_t)s * HC + lane * 4];
        ax += alpha * hv.x; ay += alpha * hv.y;
        az += alpha * hv.z; aw += alpha * hv.w;
    }
    *(float4*)&g_agg[(size_t)n * HC + lane * 4] = make_float4(ax, ay, az, aw);
}

// ---------------- kernel 6: bias + LayerNorm + FF + residual ------------------
#define LNFF_SMEM (128*128*4 + 8*128*4)
__global__ void lnff_kernel(const float* __restrict__ x,
                            const float* __restrict__ conv_bias,
                            const float* __restrict__ ln_g,
                            const float* __restrict__ ln_b,
                            const float* __restrict__ ffw,
                            const float* __restrict__ ffb,
                            float* __restrict__ out) {
    extern __shared__ float sm[];
    float* Ws = sm;              // 128x128 ff_w
    float* vs = sm + 128*128;    // 8 warps x 128 normalized values

    const int t = threadIdx.x, lane = t & 31, w = t >> 5;
    for (int i = t; i < 128*128/4; i += 256)
        ((float4*)Ws)[i] = ((const float4*)ffw)[i];
    __syncthreads();

    const int n = blockIdx.x * 8 + w;
    if (n >= N_NODES) return;

    float4 v  = *(const float4*)&g_agg[(size_t)n * HC + lane * 4];
    float4 cb = *(const float4*)&conv_bias[lane * 4];
    v.x += cb.x; v.y += cb.y; v.z += cb.z; v.w += cb.w;

    float s = v.x + v.y + v.z + v.w;
    #pragma unroll
    for (int o = 16; o > 0; o >>= 1) s += __shfl_xor_sync(0xFFFFFFFFu, s, o);
    const float mu = s * (1.0f / 128.0f);

    float dx = v.x - mu, dy = v.y - mu, dz = v.z - mu, dw = v.w - mu;
    float sq = dx*dx + dy*dy + dz*dz + dw*dw;
    #pragma unroll
    for (int o = 16; o > 0; o >>= 1) sq += __shfl_xor_sync(0xFFFFFFFFu, sq, o);
    const float rstd = rsqrtf(sq * (1.0f / 128.0f) + LN_EPS);

    float4 gg = *(const float4*)&ln_g[lane * 4];
    float4 bb = *(const float4*)&ln_b[lane * 4];
    float* vrow = &vs[w * 128];
    *(float4*)&vrow[lane * 4] = make_float4(dx*rstd*gg.x + bb.x,
                                            dy*rstd*gg.y + bb.y,
                                            dz*rstd*gg.z + bb.z,
                                            dw*rstd*gg.w + bb.w);
    __syncwarp();

    unsigned long long a0 = 0ull, a1 = 0ull;
    #pragma unroll 8
    for (int k = 0; k < 128; k++) {
        float vk = vrow[k];
        unsigned long long xx = pack2(vk, vk);
        ulonglong2 wv = *(const ulonglong2*)&Ws[k*128 + lane*4];
        fma2(a0, xx, wv.x);
        fma2(a1, xx, wv.y);
    }
    float y0, y1, y2, y3;
    unpack2(a0, y0, y1); unpack2(a1, y2, y3);

    float4 xr = *(const float4*)&x[(size_t)n * HC + lane * 4];
    float4 fb = *(const float4*)&ffb[lane * 4];
    *(float4*)&out[(size_t)n * HC + lane * 4] =
        make_float4(xr.x + y0 + fb.x, xr.y + y1 + fb.y,
                    xr.z + y2 + fb.z, xr.w + y3 + fb.w);
}

// ---------------- launch -------------------------------------------------------
extern "C" void kernel_launch(void* const* d_in, const int* in_sizes, int n_in,
                              void* d_out, int out_size) {
    const float* x        = (const float*)d_in[0];
    const int*   ei       = (const int*)  d_in[1];
    const float* W        = (const float*)d_in[2];
    const float* att_src  = (const float*)d_in[3];
    const float* att_dst  = (const float*)d_in[4];
    const float* conv_b   = (const float*)d_in[5];
    const float* ln_g     = (const float*)d_in[6];
    const float* ln_b     = (const float*)d_in[7];
    const float* ffw      = (const float*)d_in[8];
    const float* ffb      = (const float*)d_in[9];
    float*       out      = (float*)d_out;

    cudaFuncSetAttribute(gemm1_kernel, cudaFuncAttributeMaxDynamicSharedMemorySize, G1_SMEM);
    cudaFuncSetAttribute(lnff_kernel,  cudaFuncAttributeMaxDynamicSharedMemorySize, LNFF_SMEM);

    const int EB = (ET + 255) / 256;          // 3321
    const int NB = (N_NODES + 255) / 256;     // 196
    const int WB = (N_NODES * 32 + 255) / 256; // 6250 (warp per node)

    init_kernel   <<<NB, 256>>>();
    gemm1_kernel  <<<NB, 256, G1_SMEM>>>(x, W, att_src, att_dst);
    edge_exp_kernel<<<EB, 256>>>(ei);
    scan_kernel   <<<1, 1024>>>();
    csr_fill_kernel<<<EB, 256>>>(ei);
    agg_kernel    <<<WB, 256>>>(ei);
    lnff_kernel   <<<WB, 256, LNFF_SMEM>>>(x, conv_b, ln_g, ln_b, ffw, ffb, out);
}

// round 2
// speedup vs baseline: 1.3211x; 1.3211x over previous
#include <cuda_runtime.h>
#include <math.h>

#define N_NODES  50000
#define N_EDGES  800000
#define ET       (N_EDGES + N_NODES)   // edges + self loops
#define HC       128
#define NHEAD    8
#define NEG_SLOPE 0.2f
#define LN_EPS   1e-5f
#define NB       196                   // ceil(N_NODES/256)

// ---------------- scratch (device globals: no cudaMalloc allowed) ------------
__device__ float g_h  [(size_t)N_NODES * HC];     // 25.6 MB  x@W per-head features
__device__ float g_as [(size_t)N_NODES * NHEAD];  // attention logits (src part)
__device__ float g_ad [(size_t)N_NODES * NHEAD];  // attention logits (dst part)
__device__ float g_e  [(size_t)ET * NHEAD];       // 27.2 MB  per-edge exp(logit)
__device__ int   g_deg[N_NODES];
__device__ int   g_off[N_NODES];
__device__ int   g_cur[N_NODES];
__device__ int   g_bsum[256];
__device__ int   g_eid[ET];                       // CSR by destination
__device__ float g_agg[(size_t)N_NODES * HC];     // aggregated output pre-LN

// ---------------- packed f32x2 FMA helpers (sm_100+) -------------------------
__device__ __forceinline__ unsigned long long pack2(float x, float y) {
    unsigned long long r;
    asm("mov.b64 %0, {%1, %2};" : "=l"(r) : "f"(x), "f"(y));
    return r;
}
__device__ __forceinline__ void unpack2(unsigned long long v, float& x, float& y) {
    asm("mov.b64 {%0, %1}, %2;" : "=f"(x), "=f"(y) : "l"(v));
}
__device__ __forceinline__ void fma2(unsigned long long& acc,
                                     unsigned long long a, unsigned long long b) {
    asm("fma.rn.f32x2 %0, %1, %2, %0;" : "+l"(acc) : "l"(a), "l"(b));
}

// ---------------- kernel 0: init ---------------------------------------------
__global__ void init_kernel() {
    int i = blockIdx.x * blockDim.x + threadIdx.x;
    if (i < N_NODES) g_deg[i] = 0;
}

// ---------------- kernel 1: h = x@W, a_s, a_d --------------------------------
#define G1_SMEM (256*129*4 + 128*128*4 + 2*128*4)
__global__ void gemm1_kernel(const float* __restrict__ x,
                             const float* __restrict__ W,
                             const float* __restrict__ att_src,
                             const float* __restrict__ att_dst) {
    extern __shared__ float sm[];
    float* xs   = sm;                    // 256 rows, stride 129 (conflict-free)
    float* Ws   = sm + 256*129;          // 128x128
    float* as_s = Ws + 128*128;          // 128
    float* ad_s = as_s + 128;            // 128

    const int t = threadIdx.x;
    const int node0 = blockIdx.x * 256;

    for (int i = t; i < 128*128/4; i += 256)
        ((float4*)Ws)[i] = ((const float4*)W)[i];
    if (t < 128) { as_s[t] = att_src[t]; ad_s[t] = att_dst[t]; }

    for (int i = t; i < 256*32; i += 256) {
        int r = i >> 5, cq = i & 31;
        float4 v = make_float4(0.f, 0.f, 0.f, 0.f);
        if (node0 + r < N_NODES)
            v = ((const float4*)x)[(size_t)(node0 + r) * 32 + cq];
        float* d = &xs[r*129 + cq*4];
        d[0] = v.x; d[1] = v.y; d[2] = v.z; d[3] = v.w;
    }
    __syncthreads();

    const int node = node0 + t;
    if (node >= N_NODES) return;
    const float* xr = &xs[t*129];

    float as_acc[NHEAD] = {0,0,0,0,0,0,0,0};
    float ad_acc[NHEAD] = {0,0,0,0,0,0,0,0};

    for (int g = 0; g < 16; g++) {           // 16 groups of 8 output channels
        unsigned long long a0 = 0ull, a1 = 0ull, a2 = 0ull, a3 = 0ull;
        #pragma unroll 8
        for (int k = 0; k < 128; k++) {
            float xv = xr[k];
            unsigned long long xx = pack2(xv, xv);
            ulonglong2 w0 = *(const ulonglong2*)&Ws[k*128 + (g<<3)];
            ulonglong2 w1 = *(const ulonglong2*)&Ws[k*128 + (g<<3) + 4];
            fma2(a0, xx, w0.x); fma2(a1, xx, w0.y);
            fma2(a2, xx, w1.x); fma2(a3, xx, w1.y);
        }
        float acc[8];
        unpack2(a0, acc[0], acc[1]); unpack2(a1, acc[2], acc[3]);
        unpack2(a2, acc[4], acc[5]); unpack2(a3, acc[6], acc[7]);

        float* hdst = &g_h[(size_t)node * HC + (g<<3)];
        *(float4*)&hdst[0] = make_float4(acc[0], acc[1], acc[2], acc[3]);
        *(float4*)&hdst[4] = make_float4(acc[4], acc[5], acc[6], acc[7]);

        const int head = g >> 1, base = (g & 1) * 8;
        #pragma unroll
        for (int j = 0; j < 8; j++) {
            as_acc[head] += acc[j] * as_s[head*16 + base + j];
            ad_acc[head] += acc[j] * ad_s[head*16 + base + j];
        }
    }
    #pragma unroll
    for (int h = 0; h < NHEAD; h++) {
        g_as[(size_t)node*NHEAD + h] = as_acc[h];
        g_ad[(size_t)node*NHEAD + h] = ad_acc[h];
    }
}

// ---------------- kernel 2: per-edge exp(leaky(logit)) + degree histogram ----
__global__ void edge_exp_kernel(const int* __restrict__ ei) {
    int i = blockIdx.x * blockDim.x + threadIdx.x;
    if (i >= ET) return;
    int s, d;
    if (i < N_EDGES) { s = ei[i]; d = ei[N_EDGES + i]; }
    else             { s = d = i - N_EDGES; }

    float4 a0 = *(const float4*)&g_as[(size_t)s*NHEAD];
    float4 a1 = *(const float4*)&g_as[(size_t)s*NHEAD + 4];
    float4 b0 = *(const float4*)&g_ad[(size_t)d*NHEAD];
    float4 b1 = *(const float4*)&g_ad[(size_t)d*NHEAD + 4];

    float e[8] = { a0.x+b0.x, a0.y+b0.y, a0.z+b0.z, a0.w+b0.w,
                   a1.x+b1.x, a1.y+b1.y, a1.z+b1.z, a1.w+b1.w };
    #pragma unroll
    for (int h = 0; h < 8; h++) {
        float v = e[h] > 0.f ? e[h] : NEG_SLOPE * e[h];
        e[h] = expf(v);
    }
    float* dst = &g_e[(size_t)i * NHEAD];
    *(float4*)&dst[0] = make_float4(e[0], e[1], e[2], e[3]);
    *(float4*)&dst[4] = make_float4(e[4], e[5], e[6], e[7]);

    atomicAdd(&g_deg[d], 1);
}

// ---------------- kernels 3a/3b/3c: fast 3-phase exclusive scan ---------------
__device__ __forceinline__ int warp_incl_scan(int v, int lane) {
    #pragma unroll
    for (int o = 1; o < 32; o <<= 1) {
        int u = __shfl_up_sync(0xFFFFFFFFu, v, o);
        if (lane >= o) v += u;
    }
    return v;
}

__global__ void block_scan_kernel() {      // NB blocks x 256
    __shared__ int wsum[8];
    const int t = threadIdx.x, lane = t & 31, w = t >> 5;
    const int i = blockIdx.x * 256 + t;
    const int v = (i < N_NODES) ? g_deg[i] : 0;
    int s = warp_incl_scan(v, lane);
    if (lane == 31) wsum[w] = s;
    __syncthreads();
    if (t < 8) {
        int ws = wsum[t];
        #pragma unroll
        for (int o = 1; o < 8; o <<= 1) {
            int u = __shfl_up_sync(0xFFu, ws, o);
            if (t >= o) ws += u;
        }
        wsum[t] = ws;
    }
    __syncthreads();
    const int base = (w > 0) ? wsum[w - 1] : 0;
    const int incl = base + s;
    if (i < N_NODES) g_off[i] = incl - v;   // exclusive, block-local
    if (t == 255) g_bsum[blockIdx.x] = incl;
}

__global__ void bsum_scan_kernel() {       // 1 block x 256
    __shared__ int wsum[8];
    const int t = threadIdx.x, lane = t & 31, w = t >> 5;
    const int v = (t < NB) ? g_bsum[t] : 0;
    int s = warp_incl_scan(v, lane);
    if (lane == 31) wsum[w] = s;
    __syncthreads();
    if (t < 8) {
        int ws = wsum[t];
        #pragma unroll
        for (int o = 1; o < 8; o <<= 1) {
            int u = __shfl_up_sync(0xFFu, ws, o);
            if (t >= o) ws += u;
        }
        wsum[t] = ws;
    }
    __syncthreads();
    const int base = (w > 0) ? wsum[w - 1] : 0;
    g_bsum[t] = base + s - v;               // exclusive
}

__global__ void add_base_kernel() {        // NB blocks x 256
    const int i = blockIdx.x * 256 + threadIdx.x;
    if (i < N_NODES) {
        const int o = g_off[i] + g_bsum[blockIdx.x];
        g_off[i] = o;
        g_cur[i] = o;
    }
}

// ---------------- kernel 4: CSR fill ------------------------------------------
__global__ void csr_fill_kernel(const int* __restrict__ ei) {
    int i = blockIdx.x * blockDim.x + threadIdx.x;
    if (i >= ET) return;
    int d = (i < N_EDGES) ? ei[N_EDGES + i] : (i - N_EDGES);
    int pos = atomicAdd(&g_cur[d], 1);
    g_eid[pos] = i;
}

// ---------------- kernel 5: warp-per-node single-pass aggregation -------------
// out = (sum_e w*h[src]) / (sum_e w); lane -> channels [lane*4, lane*4+4).
__global__ void agg_kernel(const int* __restrict__ ei) {
    int wid  = (blockIdx.x * blockDim.x + threadIdx.x) >> 5;
    int lane = threadIdx.x & 31;
    if (wid >= N_NODES) return;
    const int n  = wid;
    const int hd = lane >> 2;
    const int start = g_off[n];
    const int end   = start + g_deg[n];

    float wsum = 0.f;
    float ax = 0.f, ay = 0.f, az = 0.f, aw = 0.f;
    #pragma unroll 2
    for (int e = start; e < end; e++) {
        int eid = g_eid[e];                              // warp-broadcast load
        int s = (eid < N_EDGES) ? ei[eid] : (eid - N_EDGES);
        float w = g_e[(size_t)eid * NHEAD + hd];
        wsum += w;
        float4 hv = *(const float4*)&g_h[(size_t)s * HC + lane * 4];
        ax += w * hv.x; ay += w * hv.y;
        az += w * hv.z; aw += w * hv.w;
    }
    const float dinv = 1.0f / wsum;
    *(float4*)&g_agg[(size_t)n * HC + lane * 4] =
        make_float4(ax * dinv, ay * dinv, az * dinv, aw * dinv);
}

// ---------------- kernel 6: bias + LayerNorm + FF + residual ------------------
// Grid-stride persistent: each block loads ff_w into SMEM once, then loops.
#define LNFF_SMEM (128*128*4 + 8*128*4)
#define LNFF_BLOCKS 444
__global__ void lnff_kernel(const float* __restrict__ x,
                            const float* __restrict__ conv_bias,
                            const float* __restrict__ ln_g,
                            const float* __restrict__ ln_b,
                            const float* __restrict__ ffw,
                            const float* __restrict__ ffb,
                            float* __restrict__ out) {
    extern __shared__ float sm[];
    float* Ws = sm;              // 128x128 ff_w
    float* vs = sm + 128*128;    // 8 warps x 128 normalized values

    const int t = threadIdx.x, lane = t & 31, w = t >> 5;
    for (int i = t; i < 128*128/4; i += 256)
        ((float4*)Ws)[i] = ((const float4*)ffw)[i];
    __syncthreads();

    const float4 cb = *(const float4*)&conv_bias[lane * 4];
    const float4 gg = *(const float4*)&ln_g[lane * 4];
    const float4 bb = *(const float4*)&ln_b[lane * 4];
    const float4 fb = *(const float4*)&ffb[lane * 4];
    float* vrow = &vs[w * 128];

    for (int n0 = blockIdx.x * 8; n0 < N_NODES; n0 += gridDim.x * 8) {
        const int n = n0 + w;
        if (n >= N_NODES) continue;

        float4 v = *(const float4*)&g_agg[(size_t)n * HC + lane * 4];
        v.x += cb.x; v.y += cb.y; v.z += cb.z; v.w += cb.w;

        float s = v.x + v.y + v.z + v.w;
        #pragma unroll
        for (int o = 16; o > 0; o >>= 1) s += __shfl_xor_sync(0xFFFFFFFFu, s, o);
        const float mu = s * (1.0f / 128.0f);

        float dx = v.x - mu, dy = v.y - mu, dz = v.z - mu, dw = v.w - mu;
        float sq = dx*dx + dy*dy + dz*dz + dw*dw;
        #pragma unroll
        for (int o = 16; o > 0; o >>= 1) sq += __shfl_xor_sync(0xFFFFFFFFu, sq, o);
        const float rstd = rsqrtf(sq * (1.0f / 128.0f) + LN_EPS);

        *(float4*)&vrow[lane * 4] = make_float4(dx*rstd*gg.x + bb.x,
                                                dy*rstd*gg.y + bb.y,
                                                dz*rstd*gg.z + bb.z,
                                                dw*rstd*gg.w + bb.w);
        __syncwarp();

        unsigned long long a0 = 0ull, a1 = 0ull;
        #pragma unroll 8
        for (int k = 0; k < 128; k++) {
            float vk = vrow[k];
            unsigned long long xx = pack2(vk, vk);
            ulonglong2 wv = *(const ulonglong2*)&Ws[k*128 + lane*4];
            fma2(a0, xx, wv.x);
            fma2(a1, xx, wv.y);
        }
        float y0, y1, y2, y3;
        unpack2(a0, y0, y1); unpack2(a1, y2, y3);

        float4 xr = *(const float4*)&x[(size_t)n * HC + lane * 4];
        *(float4*)&out[(size_t)n * HC + lane * 4] =
            make_float4(xr.x + y0 + fb.x, xr.y + y1 + fb.y,
                        xr.z + y2 + fb.z, xr.w + y3 + fb.w);
        __syncwarp();
    }
}

// ---------------- launch -------------------------------------------------------
extern "C" void kernel_launch(void* const* d_in, const int* in_sizes, int n_in,
                              void* d_out, int out_size) {
    const float* x        = (const float*)d_in[0];
    const int*   ei       = (const int*)  d_in[1];
    const float* W        = (const float*)d_in[2];
    const float* att_src  = (const float*)d_in[3];
    const float* att_dst  = (const float*)d_in[4];
    const float* conv_b   = (const float*)d_in[5];
    const float* ln_g     = (const float*)d_in[6];
    const float* ln_b     = (const float*)d_in[7];
    const float* ffw      = (const float*)d_in[8];
    const float* ffb      = (const float*)d_in[9];
    float*       out      = (float*)d_out;

    cudaFuncSetAttribute(gemm1_kernel, cudaFuncAttributeMaxDynamicSharedMemorySize, G1_SMEM);
    cudaFuncSetAttribute(lnff_kernel,  cudaFuncAttributeMaxDynamicSharedMemorySize, LNFF_SMEM);

    const int EB = (ET + 255) / 256;           // 3321
    const int WB = (N_NODES * 32 + 255) / 256; // 6250 (warp per node)

    init_kernel    <<<NB, 256>>>();
    gemm1_kernel   <<<NB, 256, G1_SMEM>>>(x, W, att_src, att_dst);
    edge_exp_kernel<<<EB, 256>>>(ei);
    block_scan_kernel<<<NB, 256>>>();
    bsum_scan_kernel <<<1, 256>>>();
    add_base_kernel  <<<NB, 256>>>();
    csr_fill_kernel<<<EB, 256>>>(ei);
    agg_kernel     <<<WB, 256>>>(ei);
    lnff_kernel    <<<LNFF_BLOCKS, 256, LNFF_SMEM>>>(x, conv_b, ln_g, ln_b, ffw, ffb, out);
}

// round 3
// speedup vs baseline: 1.4288x; 1.0815x over previous
#include <cuda_runtime.h>
#include <math.h>

#define N_NODES  50000
#define N_EDGES  800000
#define ET       (N_EDGES + N_NODES)   // edges + self loops
#define HC       128
#define NHEAD    8
#define NEG_SLOPE 0.2f
#define LN_EPS   1e-5f
#define NB       196                   // ceil(N_NODES/256)

// ---------------- scratch (device globals: no cudaMalloc allowed) ------------
__device__ float g_h  [(size_t)N_NODES * HC];     // 25.6 MB  x@W per-head features
__device__ float g_as [(size_t)N_NODES * NHEAD];  // attention logits (src part)
__device__ float g_ad [(size_t)N_NODES * NHEAD];  // attention logits (dst part)
__device__ int   g_deg[N_NODES];
__device__ int   g_off[N_NODES];
__device__ int   g_cur[N_NODES];
__device__ int   g_bsum[256];
__device__ int   g_src[ET];                       // CSR by destination: source ids
__device__ float g_agg[(size_t)N_NODES * HC];     // aggregated output pre-LN

// ---------------- packed f32x2 FMA helpers (sm_100+) -------------------------
__device__ __forceinline__ unsigned long long pack2(float x, float y) {
    unsigned long long r;
    asm("mov.b64 %0, {%1, %2};" : "=l"(r) : "f"(x), "f"(y));
    return r;
}
__device__ __forceinline__ void unpack2(unsigned long long v, float& x, float& y) {
    asm("mov.b64 {%0, %1}, %2;" : "=f"(x), "=f"(y) : "l"(v));
}
__device__ __forceinline__ void fma2(unsigned long long& acc,
                                     unsigned long long a, unsigned long long b) {
    asm("fma.rn.f32x2 %0, %1, %2, %0;" : "+l"(acc) : "l"(a), "l"(b));
}

// ---------------- kernel 1: h = x@W, a_s, a_d --------------------------------
#define G1_SMEM (256*129*4 + 128*128*4 + 2*128*4)
__global__ void gemm1_kernel(const float* __restrict__ x,
                             const float* __restrict__ W,
                             const float* __restrict__ att_src,
                             const float* __restrict__ att_dst) {
    extern __shared__ float sm[];
    float* xs   = sm;                    // 256 rows, stride 129 (conflict-free)
    float* Ws   = sm + 256*129;          // 128x128
    float* as_s = Ws + 128*128;          // 128
    float* ad_s = as_s + 128;            // 128

    const int t = threadIdx.x;
    const int node0 = blockIdx.x * 256;

    for (int i = t; i < 128*128/4; i += 256)
        ((float4*)Ws)[i] = ((const float4*)W)[i];
    if (t < 128) { as_s[t] = att_src[t]; ad_s[t] = att_dst[t]; }

    for (int i = t; i < 256*32; i += 256) {
        int r = i >> 5, cq = i & 31;
        float4 v = make_float4(0.f, 0.f, 0.f, 0.f);
        if (node0 + r < N_NODES)
            v = ((const float4*)x)[(size_t)(node0 + r) * 32 + cq];
        float* d = &xs[r*129 + cq*4];
        d[0] = v.x; d[1] = v.y; d[2] = v.z; d[3] = v.w;
    }
    __syncthreads();

    const int node = node0 + t;
    if (node >= N_NODES) return;
    const float* xr = &xs[t*129];

    float as_acc[NHEAD] = {0,0,0,0,0,0,0,0};
    float ad_acc[NHEAD] = {0,0,0,0,0,0,0,0};

    for (int g = 0; g < 16; g++) {           // 16 groups of 8 output channels
        unsigned long long a0 = 0ull, a1 = 0ull, a2 = 0ull, a3 = 0ull;
        #pragma unroll 8
        for (int k = 0; k < 128; k++) {
            float xv = xr[k];
            unsigned long long xx = pack2(xv, xv);
            ulonglong2 w0 = *(const ulonglong2*)&Ws[k*128 + (g<<3)];
            ulonglong2 w1 = *(const ulonglong2*)&Ws[k*128 + (g<<3) + 4];
            fma2(a0, xx, w0.x); fma2(a1, xx, w0.y);
            fma2(a2, xx, w1.x); fma2(a3, xx, w1.y);
        }
        float acc[8];
        unpack2(a0, acc[0], acc[1]); unpack2(a1, acc[2], acc[3]);
        unpack2(a2, acc[4], acc[5]); unpack2(a3, acc[6], acc[7]);

        float* hdst = &g_h[(size_t)node * HC + (g<<3)];
        *(float4*)&hdst[0] = make_float4(acc[0], acc[1], acc[2], acc[3]);
        *(float4*)&hdst[4] = make_float4(acc[4], acc[5], acc[6], acc[7]);

        const int head = g >> 1, base = (g & 1) * 8;
        #pragma unroll
        for (int j = 0; j < 8; j++) {
            as_acc[head] += acc[j] * as_s[head*16 + base + j];
            ad_acc[head] += acc[j] * ad_s[head*16 + base + j];
        }
    }
    #pragma unroll
    for (int h = 0; h < NHEAD; h++) {
        g_as[(size_t)node*NHEAD + h] = as_acc[h];
        g_ad[(size_t)node*NHEAD + h] = ad_acc[h];
    }
}

// ---------------- kernel 2: degree histogram ----------------------------------
__global__ void hist_kernel(const int* __restrict__ ei) {
    int i = blockIdx.x * blockDim.x + threadIdx.x;
    if (i >= ET) return;
    int d = (i < N_EDGES) ? ei[N_EDGES + i] : (i - N_EDGES);
    atomicAdd(&g_deg[d], 1);
}

// ---------------- kernels 3a/3b/3c: 3-phase exclusive scan --------------------
__device__ __forceinline__ int warp_incl_scan(int v, int lane) {
    #pragma unroll
    for (int o = 1; o < 32; o <<= 1) {
        int u = __shfl_up_sync(0xFFFFFFFFu, v, o);
        if (lane >= o) v += u;
    }
    return v;
}

__global__ void block_scan_kernel() {      // NB blocks x 256
    __shared__ int wsum[8];
    const int t = threadIdx.x, lane = t & 31, w = t >> 5;
    const int i = blockIdx.x * 256 + t;
    const int v = (i < N_NODES) ? g_deg[i] : 0;
    int s = warp_incl_scan(v, lane);
    if (lane == 31) wsum[w] = s;
    __syncthreads();
    if (t < 8) {
        int ws = wsum[t];
        #pragma unroll
        for (int o = 1; o < 8; o <<= 1) {
            int u = __shfl_up_sync(0xFFu, ws, o);
            if (t >= o) ws += u;
        }
        wsum[t] = ws;
    }
    __syncthreads();
    const int base = (w > 0) ? wsum[w - 1] : 0;
    const int incl = base + s;
    if (i < N_NODES) g_off[i] = incl - v;   // exclusive, block-local
    if (t == 255) g_bsum[blockIdx.x] = incl;
}

__global__ void bsum_scan_kernel() {       // 1 block x 256
    __shared__ int wsum[8];
    const int t = threadIdx.x, lane = t & 31, w = t >> 5;
    const int v = (t < NB) ? g_bsum[t] : 0;
    int s = warp_incl_scan(v, lane);
    if (lane == 31) wsum[w] = s;
    __syncthreads();
    if (t < 8) {
        int ws = wsum[t];
        #pragma unroll
        for (int o = 1; o < 8; o <<= 1) {
            int u = __shfl_up_sync(0xFFu, ws, o);
            if (t >= o) ws += u;
        }
        wsum[t] = ws;
    }
    __syncthreads();
    const int base = (w > 0) ? wsum[w - 1] : 0;
    g_bsum[t] = base + s - v;               // exclusive
}

__global__ void add_base_kernel() {        // NB blocks x 256
    const int i = blockIdx.x * 256 + threadIdx.x;
    if (i < N_NODES) {
        const int o = g_off[i] + g_bsum[blockIdx.x];
        g_off[i] = o;
        g_cur[i] = o;
    }
}

// ---------------- kernel 4: CSR fill (payload = source node id) ---------------
__global__ void csr_fill_kernel(const int* __restrict__ ei) {
    int i = blockIdx.x * blockDim.x + threadIdx.x;
    if (i >= ET) return;
    int s, d;
    if (i < N_EDGES) { s = ei[i]; d = ei[N_EDGES + i]; }
    else             { s = d = i - N_EDGES; }
    int pos = atomicAdd(&g_cur[d], 1);
    g_src[pos] = s;
}

// ---------------- kernel 5: warp-per-node aggregation with inline softmax -----
// w = exp(leaky(a_s[s]+a_d[n])) recomputed per edge (no segment max needed:
// logits are O(10); exp(e)/sum == shifted form mathematically).
// out = (sum_e w*h[s]) / (sum_e w). lane -> channels [lane*4, lane*4+4).
__global__ void agg_kernel() {
    int wid  = (blockIdx.x * blockDim.x + threadIdx.x) >> 5;
    int lane = threadIdx.x & 31;
    if (wid >= N_NODES) return;
    const int n  = wid;
    const int hd = lane >> 2;
    const int start = g_off[n];
    const int end   = start + g_deg[n];

    const float ad = g_ad[(size_t)n * NHEAD + hd];   // loop-invariant

    float wsum = 0.f;
    float ax = 0.f, ay = 0.f, az = 0.f, aw = 0.f;
    #pragma unroll 2
    for (int e = start; e < end; e++) {
        int s = g_src[e];                            // sequential, warp-broadcast
        float lg = g_as[(size_t)s * NHEAD + hd] + ad;
        lg = lg > 0.f ? lg : NEG_SLOPE * lg;
        float w = __expf(lg) ;
        // __expf == exp2(x*log2e) via MUFU; max |lg| ~ 12 -> well within
        // MUFU.EX2 exact range; relative error ~1e-7, same class as expf.
        wsum += w;
        float4 hv = *(const float4*)&g_h[(size_t)s * HC + lane * 4];
        ax += w * hv.x; ay += w * hv.y;
        az += w * hv.z; aw += w * hv.w;
    }
    const float dinv = 1.0f / wsum;
    *(float4*)&g_agg[(size_t)n * HC + lane * 4] =
        make_float4(ax * dinv, ay * dinv, az * dinv, aw * dinv);
}

// ---------------- kernel 6: bias + LayerNorm + FF + residual ------------------
#define LNFF_SMEM (128*128*4 + 8*128*4)
#define LNFF_BLOCKS 444
__global__ void lnff_kernel(const float* __restrict__ x,
                            const float* __restrict__ conv_bias,
                            const float* __restrict__ ln_g,
                            const float* __restrict__ ln_b,
                            const float* __restrict__ ffw,
                            const float* __restrict__ ffb,
                            float* __restrict__ out) {
    extern __shared__ float sm[];
    float* Ws = sm;              // 128x128 ff_w
    float* vs = sm + 128*128;    // 8 warps x 128 normalized values

    const int t = threadIdx.x, lane = t & 31, w = t >> 5;
    for (int i = t; i < 128*128/4; i += 256)
        ((float4*)Ws)[i] = ((const float4*)ffw)[i];
    __syncthreads();

    const float4 cb = *(const float4*)&conv_bias[lane * 4];
    const float4 gg = *(const float4*)&ln_g[lane * 4];
    const float4 bb = *(const float4*)&ln_b[lane * 4];
    const float4 fb = *(const float4*)&ffb[lane * 4];
    float* vrow = &vs[w * 128];

    for (int n0 = blockIdx.x * 8; n0 < N_NODES; n0 += gridDim.x * 8) {
        const int n = n0 + w;
        if (n >= N_NODES) continue;

        float4 v = *(const float4*)&g_agg[(size_t)n * HC + lane * 4];
        v.x += cb.x; v.y += cb.y; v.z += cb.z; v.w += cb.w;

        float s = v.x + v.y + v.z + v.w;
        #pragma unroll
        for (int o = 16; o > 0; o >>= 1) s += __shfl_xor_sync(0xFFFFFFFFu, s, o);
        const float mu = s * (1.0f / 128.0f);

        float dx = v.x - mu, dy = v.y - mu, dz = v.z - mu, dw = v.w - mu;
        float sq = dx*dx + dy*dy + dz*dz + dw*dw;
        #pragma unroll
        for (int o = 16; o > 0; o >>= 1) sq += __shfl_xor_sync(0xFFFFFFFFu, sq, o);
        const float rstd = rsqrtf(sq * (1.0f / 128.0f) + LN_EPS);

        *(float4*)&vrow[lane * 4] = make_float4(dx*rstd*gg.x + bb.x,
                                                dy*rstd*gg.y + bb.y,
                                                dz*rstd*gg.z + bb.z,
                                                dw*rstd*gg.w + bb.w);
        __syncwarp();

        unsigned long long a0 = 0ull, a1 = 0ull;
        #pragma unroll 8
        for (int k = 0; k < 128; k++) {
            float vk = vrow[k];
            unsigned long long xx = pack2(vk, vk);
            ulonglong2 wv = *(const ulonglong2*)&Ws[k*128 + lane*4];
            fma2(a0, xx, wv.x);
            fma2(a1, xx, wv.y);
        }
        float y0, y1, y2, y3;
        unpack2(a0, y0, y1); unpack2(a1, y2, y3);

        float4 xr = *(const float4*)&x[(size_t)n * HC + lane * 4];
        *(float4*)&out[(size_t)n * HC + lane * 4] =
            make_float4(xr.x + y0 + fb.x, xr.y + y1 + fb.y,
                        xr.z + y2 + fb.z, xr.w + y3 + fb.w);
        __syncwarp();
    }
}

// ---------------- launch -------------------------------------------------------
extern "C" void kernel_launch(void* const* d_in, const int* in_sizes, int n_in,
                              void* d_out, int out_size) {
    const float* x        = (const float*)d_in[0];
    const int*   ei       = (const int*)  d_in[1];
    const float* W        = (const float*)d_in[2];
    const float* att_src  = (const float*)d_in[3];
    const float* att_dst  = (const float*)d_in[4];
    const float* conv_b   = (const float*)d_in[5];
    const float* ln_g     = (const float*)d_in[6];
    const float* ln_b     = (const float*)d_in[7];
    const float* ffw      = (const float*)d_in[8];
    const float* ffb      = (const float*)d_in[9];
    float*       out      = (float*)d_out;

    cudaFuncSetAttribute(gemm1_kernel, cudaFuncAttributeMaxDynamicSharedMemorySize, G1_SMEM);
    cudaFuncSetAttribute(lnff_kernel,  cudaFuncAttributeMaxDynamicSharedMemorySize, LNFF_SMEM);

    const int EB = (ET + 255) / 256;           // 3321
    const int WB = (N_NODES * 32 + 255) / 256; // 6250 (warp per node)

    void* deg_ptr = nullptr;
    cudaGetSymbolAddress(&deg_ptr, g_deg);
    cudaMemsetAsync(deg_ptr, 0, (size_t)N_NODES * sizeof(int));

    gemm1_kernel   <<<NB, 256, G1_SMEM>>>(x, W, att_src, att_dst);
    hist_kernel    <<<EB, 256>>>(ei);
    block_scan_kernel<<<NB, 256>>>();
    bsum_scan_kernel <<<1, 256>>>();
    add_base_kernel  <<<NB, 256>>>();
    csr_fill_kernel<<<EB, 256>>>(ei);
    agg_kernel     <<<WB, 256>>>();
    lnff_kernel    <<<LNFF_BLOCKS, 256, LNFF_SMEM>>>(x, conv_b, ln_g, ln_b, ffw, ffb, out);
}

// round 4
// speedup vs baseline: 1.4295x; 1.0004x over previous
#include <cuda_runtime.h>
#include <math.h>

#define N_NODES  50000
#define N_EDGES  800000
#define ET       (N_EDGES + N_NODES)   // edges + self loops
#define HC       128
#define NHEAD    8
#define NEG_SLOPE 0.2f
#define LN_EPS   1e-5f
#define NB       196                   // ceil(N_NODES/256)

// ---------------- scratch (device globals: no cudaMalloc allowed) ------------
__device__ float g_h  [(size_t)N_NODES * HC];     // 25.6 MB  x@W per-head features
__device__ float g_as [(size_t)N_NODES * NHEAD];  // attention logits (src part)
__device__ float g_ad [(size_t)N_NODES * NHEAD];  // attention logits (dst part)
__device__ int   g_deg[N_NODES];
__device__ int   g_off[N_NODES];
__device__ int   g_cur[N_NODES];
__device__ int   g_bsum[256];                     // lookback: block_total+1, 0 = not ready
__device__ int   g_src[ET];                       // CSR by destination: source ids

// ---------------- packed f32x2 FMA helpers (sm_100+) -------------------------
__device__ __forceinline__ unsigned long long pack2(float x, float y) {
    unsigned long long r;
    asm("mov.b64 %0, {%1, %2};" : "=l"(r) : "f"(x), "f"(y));
    return r;
}
__device__ __forceinline__ void unpack2(unsigned long long v, float& x, float& y) {
    asm("mov.b64 {%0, %1}, %2;" : "=f"(x), "=f"(y) : "l"(v));
}
__device__ __forceinline__ void fma2(unsigned long long& acc,
                                     unsigned long long a, unsigned long long b) {
    asm("fma.rn.f32x2 %0, %1, %2, %0;" : "+l"(acc) : "l"(a), "l"(b));
}

// ---------------- kernel 1: h = x@W, a_s, a_d --------------------------------
#define G1_SMEM (256*129*4 + 128*128*4 + 2*128*4)
__global__ void gemm1_kernel(const float* __restrict__ x,
                             const float* __restrict__ W,
                             const float* __restrict__ att_src,
                             const float* __restrict__ att_dst) {
    extern __shared__ float sm[];
    float* xs   = sm;                    // 256 rows, stride 129 (conflict-free)
    float* Ws   = sm + 256*129;          // 128x128
    float* as_s = Ws + 128*128;          // 128
    float* ad_s = as_s + 128;            // 128

    const int t = threadIdx.x;
    const int node0 = blockIdx.x * 256;

    for (int i = t; i < 128*128/4; i += 256)
        ((float4*)Ws)[i] = ((const float4*)W)[i];
    if (t < 128) { as_s[t] = att_src[t]; ad_s[t] = att_dst[t]; }

    for (int i = t; i < 256*32; i += 256) {
        int r = i >> 5, cq = i & 31;
        float4 v = make_float4(0.f, 0.f, 0.f, 0.f);
        if (node0 + r < N_NODES)
            v = ((const float4*)x)[(size_t)(node0 + r) * 32 + cq];
        float* d = &xs[r*129 + cq*4];
        d[0] = v.x; d[1] = v.y; d[2] = v.z; d[3] = v.w;
    }
    __syncthreads();

    const int node = node0 + t;
    if (node >= N_NODES) return;
    const float* xr = &xs[t*129];

    float as_acc[NHEAD] = {0,0,0,0,0,0,0,0};
    float ad_acc[NHEAD] = {0,0,0,0,0,0,0,0};

    for (int g = 0; g < 16; g++) {           // 16 groups of 8 output channels
        unsigned long long a0 = 0ull, a1 = 0ull, a2 = 0ull, a3 = 0ull;
        #pragma unroll 8
        for (int k = 0; k < 128; k++) {
            float xv = xr[k];
            unsigned long long xx = pack2(xv, xv);
            ulonglong2 w0 = *(const ulonglong2*)&Ws[k*128 + (g<<3)];
            ulonglong2 w1 = *(const ulonglong2*)&Ws[k*128 + (g<<3) + 4];
            fma2(a0, xx, w0.x); fma2(a1, xx, w0.y);
            fma2(a2, xx, w1.x); fma2(a3, xx, w1.y);
        }
        float acc[8];
        unpack2(a0, acc[0], acc[1]); unpack2(a1, acc[2], acc[3]);
        unpack2(a2, acc[4], acc[5]); unpack2(a3, acc[6], acc[7]);

        float* hdst = &g_h[(size_t)node * HC + (g<<3)];
        *(float4*)&hdst[0] = make_float4(acc[0], acc[1], acc[2], acc[3]);
        *(float4*)&hdst[4] = make_float4(acc[4], acc[5], acc[6], acc[7]);

        const int head = g >> 1, base = (g & 1) * 8;
        #pragma unroll
        for (int j = 0; j < 8; j++) {
            as_acc[head] += acc[j] * as_s[head*16 + base + j];
            ad_acc[head] += acc[j] * ad_s[head*16 + base + j];
        }
    }
    #pragma unroll
    for (int h = 0; h < NHEAD; h++) {
        g_as[(size_t)node*NHEAD + h] = as_acc[h];
        g_ad[(size_t)node*NHEAD + h] = ad_acc[h];
    }
}

// ---------------- kernel 2: degree histogram ----------------------------------
__global__ void hist_kernel(const int* __restrict__ ei) {
    int i = blockIdx.x * blockDim.x + threadIdx.x;
    if (i >= ET) return;
    int d = (i < N_EDGES) ? ei[N_EDGES + i] : (i - N_EDGES);
    atomicAdd(&g_deg[d], 1);
}

// ---------------- kernel 3: single-pass decoupled-lookback exclusive scan -----
__device__ __forceinline__ int warp_incl_scan(int v, int lane) {
    #pragma unroll
    for (int o = 1; o < 32; o <<= 1) {
        int u = __shfl_up_sync(0xFFFFFFFFu, v, o);
        if (lane >= o) v += u;
    }
    return v;
}

__global__ void scan_kernel() {      // NB blocks x 256, all resident in wave 1
    __shared__ int wsum[8];
    __shared__ int base_sh;
    const int t = threadIdx.x, lane = t & 31, w = t >> 5;
    const int b = blockIdx.x;
    const int i = b * 256 + t;
    const int v = (i < N_NODES) ? g_deg[i] : 0;
    int s = warp_incl_scan(v, lane);
    if (lane == 31) wsum[w] = s;
    __syncthreads();
    if (t < 8) {
        int ws = wsum[t];
        #pragma unroll
        for (int o = 1; o < 8; o <<= 1) {
            int u = __shfl_up_sync(0xFFu, ws, o);
            if (t >= o) ws += u;
        }
        wsum[t] = ws;
    }
    __syncthreads();
    const int incl = ((w > 0) ? wsum[w - 1] : 0) + s;

    // publish block total (tagged +1 so 0 means "not ready")
    if (t == 255) atomicExch(&g_bsum[b], incl + 1);

    // lookback: warp 0 sums all predecessor totals
    if (w == 0) {
        int sum = 0;
        for (int p = b - 1 - lane; p >= 0; p -= 32) {
            int val;
            do { val = atomicAdd(&g_bsum[p], 0); } while (val == 0);
            sum += val - 1;
        }
        #pragma unroll
        for (int o = 16; o > 0; o >>= 1) sum += __shfl_xor_sync(0xFFFFFFFFu, sum, o);
        if (lane == 0) base_sh = sum;
    }
    __syncthreads();

    if (i < N_NODES) {
        const int off = base_sh + incl - v;
        g_off[i] = off;
        g_cur[i] = off;
    }
}

// ---------------- kernel 4: CSR fill (payload = source node id) ---------------
__global__ void csr_fill_kernel(const int* __restrict__ ei) {
    int i = blockIdx.x * blockDim.x + threadIdx.x;
    if (i >= ET) return;
    int s, d;
    if (i < N_EDGES) { s = ei[i]; d = ei[N_EDGES + i]; }
    else             { s = d = i - N_EDGES; }
    int pos = atomicAdd(&g_cur[d], 1);
    g_src[pos] = s;
}

// ---------------- kernel 5: fused aggregation + bias + LN + FF + residual -----
// Persistent grid-stride; warp-per-node. lane -> channels [lane*4, lane*4+4),
// head = lane>>2. Attention weight recomputed inline:
//   w = exp(leaky(a_s[s] + a_d[n])); out = (sum w*h[s]) / (sum w)
// (segment-max omitted: logits are O(10), exp() safely in fp32 range, and the
//  softmax is shift-invariant mathematically.)
#define FUSE_SMEM (128*128*4 + 8*128*4)
#define FUSE_BLOCKS 444
__global__ void fused_agg_lnff_kernel(const float* __restrict__ x,
                                      const float* __restrict__ conv_bias,
                                      const float* __restrict__ ln_g,
                                      const float* __restrict__ ln_b,
                                      const float* __restrict__ ffw,
                                      const float* __restrict__ ffb,
                                      float* __restrict__ out) {
    extern __shared__ float sm[];
    float* Ws = sm;              // 128x128 ff_w
    float* vs = sm + 128*128;    // 8 warps x 128 normalized values

    const int t = threadIdx.x, lane = t & 31, w = t >> 5;
    const int hd = lane >> 2;

    for (int i = t; i < 128*128/4; i += 256)
        ((float4*)Ws)[i] = ((const float4*)ffw)[i];
    __syncthreads();

    const float4 cb = *(const float4*)&conv_bias[lane * 4];
    const float4 gg = *(const float4*)&ln_g[lane * 4];
    const float4 bb = *(const float4*)&ln_b[lane * 4];
    const float4 fb = *(const float4*)&ffb[lane * 4];
    float* vrow = &vs[w * 128];

    for (int n0 = blockIdx.x * 8; n0 < N_NODES; n0 += gridDim.x * 8) {
        const int n = n0 + w;
        if (n >= N_NODES) continue;

        const int start = g_off[n];
        const int end   = start + g_deg[n];
        const float ad  = g_ad[(size_t)n * NHEAD + hd];

        float wsum = 0.f;
        float ax = 0.f, ay = 0.f, az = 0.f, aw = 0.f;

        int e = start;
        for (; e + 4 <= end; e += 4) {          // MLP: 4 independent gathers
            const int s0 = g_src[e], s1 = g_src[e+1];
            const int s2 = g_src[e+2], s3 = g_src[e+3];
            float l0 = g_as[(size_t)s0 * NHEAD + hd] + ad;
            float l1 = g_as[(size_t)s1 * NHEAD + hd] + ad;
            float l2 = g_as[(size_t)s2 * NHEAD + hd] + ad;
            float l3 = g_as[(size_t)s3 * NHEAD + hd] + ad;
            float4 h0 = *(const float4*)&g_h[(size_t)s0 * HC + lane * 4];
            float4 h1 = *(const float4*)&g_h[(size_t)s1 * HC + lane * 4];
            float4 h2 = *(const float4*)&g_h[(size_t)s2 * HC + lane * 4];
            float4 h3 = *(const float4*)&g_h[(size_t)s3 * HC + lane * 4];
            l0 = l0 > 0.f ? l0 : NEG_SLOPE * l0;
            l1 = l1 > 0.f ? l1 : NEG_SLOPE * l1;
            l2 = l2 > 0.f ? l2 : NEG_SLOPE * l2;
            l3 = l3 > 0.f ? l3 : NEG_SLOPE * l3;
            const float w0 = __expf(l0), w1 = __expf(l1);
            const float w2 = __expf(l2), w3 = __expf(l3);
            wsum += (w0 + w1) + (w2 + w3);
            ax += w0*h0.x + w1*h1.x + w2*h2.x + w3*h3.x;
            ay += w0*h0.y + w1*h1.y + w2*h2.y + w3*h3.y;
            az += w0*h0.z + w1*h1.z + w2*h2.z + w3*h3.z;
            aw += w0*h0.w + w1*h1.w + w2*h2.w + w3*h3.w;
        }
        for (; e < end; e++) {
            const int s = g_src[e];
            float lg = g_as[(size_t)s * NHEAD + hd] + ad;
            lg = lg > 0.f ? lg : NEG_SLOPE * lg;
            const float ww = __expf(lg);
            wsum += ww;
            float4 hv = *(const float4*)&g_h[(size_t)s * HC + lane * 4];
            ax += ww * hv.x; ay += ww * hv.y;
            az += ww * hv.z; aw += ww * hv.w;
        }

        const float dinv = 1.0f / wsum;
        float4 v = make_float4(ax * dinv + cb.x, ay * dinv + cb.y,
                               az * dinv + cb.z, aw * dinv + cb.w);

        // LayerNorm across the warp's 128 channels
        float s = v.x + v.y + v.z + v.w;
        #pragma unroll
        for (int o = 16; o > 0; o >>= 1) s += __shfl_xor_sync(0xFFFFFFFFu, s, o);
        const float mu = s * (1.0f / 128.0f);

        float dx = v.x - mu, dy = v.y - mu, dz = v.z - mu, dw = v.w - mu;
        float sq = dx*dx + dy*dy + dz*dz + dw*dw;
        #pragma unroll
        for (int o = 16; o > 0; o >>= 1) sq += __shfl_xor_sync(0xFFFFFFFFu, sq, o);
        const float rstd = rsqrtf(sq * (1.0f / 128.0f) + LN_EPS);

        *(float4*)&vrow[lane * 4] = make_float4(dx*rstd*gg.x + bb.x,
                                                dy*rstd*gg.y + bb.y,
                                                dz*rstd*gg.z + bb.z,
                                                dw*rstd*gg.w + bb.w);
        __syncwarp();

        // FF: y = vrow @ ff_w (each lane: 4 output channels)
        unsigned long long a0 = 0ull, a1 = 0ull;
        #pragma unroll 8
        for (int k = 0; k < 128; k++) {
            float vk = vrow[k];
            unsigned long long xx = pack2(vk, vk);
            ulonglong2 wv = *(const ulonglong2*)&Ws[k*128 + lane*4];
            fma2(a0, xx, wv.x);
            fma2(a1, xx, wv.y);
        }
        float y0, y1, y2, y3;
        unpack2(a0, y0, y1); unpack2(a1, y2, y3);

        float4 xr = *(const float4*)&x[(size_t)n * HC + lane * 4];
        *(float4*)&out[(size_t)n * HC + lane * 4] =
            make_float4(xr.x + y0 + fb.x, xr.y + y1 + fb.y,
                        xr.z + y2 + fb.z, xr.w + y3 + fb.w);
        __syncwarp();
    }
}

// ---------------- launch -------------------------------------------------------
extern "C" void kernel_launch(void* const* d_in, const int* in_sizes, int n_in,
                              void* d_out, int out_size) {
    const float* x        = (const float*)d_in[0];
    const int*   ei       = (const int*)  d_in[1];
    const float* W        = (const float*)d_in[2];
    const float* att_src  = (const float*)d_in[3];
    const float* att_dst  = (const float*)d_in[4];
    const float* conv_b   = (const float*)d_in[5];
    const float* ln_g     = (const float*)d_in[6];
    const float* ln_b     = (const float*)d_in[7];
    const float* ffw      = (const float*)d_in[8];
    const float* ffb      = (const float*)d_in[9];
    float*       out      = (float*)d_out;

    cudaFuncSetAttribute(gemm1_kernel, cudaFuncAttributeMaxDynamicSharedMemorySize, G1_SMEM);
    cudaFuncSetAttribute(fused_agg_lnff_kernel,
                         cudaFuncAttributeMaxDynamicSharedMemorySize, FUSE_SMEM);

    const int EB = (ET + 255) / 256;           // 3321

    void* deg_ptr = nullptr;  cudaGetSymbolAddress(&deg_ptr,  g_deg);
    void* bsum_ptr = nullptr; cudaGetSymbolAddress(&bsum_ptr, g_bsum);
    cudaMemsetAsync(deg_ptr,  0, (size_t)N_NODES * sizeof(int));
    cudaMemsetAsync(bsum_ptr, 0, 256 * sizeof(int));

    gemm1_kernel   <<<NB, 256, G1_SMEM>>>(x, W, att_src, att_dst);
    hist_kernel    <<<EB, 256>>>(ei);
    scan_kernel    <<<NB, 256>>>();
    csr_fill_kernel<<<EB, 256>>>(ei);
    fused_agg_lnff_kernel<<<FUSE_BLOCKS, 256, FUSE_SMEM>>>(
        x, conv_b, ln_g, ln_b, ffw, ffb, out);
}

// round 6
// speedup vs baseline: 2.4765x; 1.7324x over previous
#include <cuda_runtime.h>
#include <cuda_bf16.h>
#include <math.h>
#include <stdint.h>

#define N_NODES  50000
#define N_EDGES  800000
#define ET       (N_EDGES + N_NODES)   // edges + self loops
#define HC       128
#define NHEAD    8
#define NEG_SLOPE 0.2f
#define LN_EPS   1e-5f
#define NB       196                   // ceil(N_NODES/256)
#define GEMM_BLOCKS 391                // ceil(N_NODES/128)

// ---------------- scratch (device globals: no cudaMalloc allowed) ------------
__device__ float g_h  [(size_t)N_NODES * HC];     // x@W per-head features (fp32)
__device__ float g_v  [(size_t)N_NODES * HC];     // normalized LN output (fp32)
__device__ float g_as [(size_t)N_NODES * NHEAD];
__device__ float g_ad [(size_t)N_NODES * NHEAD];
__device__ int   g_deg[N_NODES];
__device__ int   g_off[N_NODES];
__device__ int   g_cur[N_NODES];
__device__ int   g_bsum[256];                     // lookback scan state
__device__ int   g_src[ET];                       // CSR by destination: source ids
// weight images: [128 n][68 u32] (64 used, stride-68 pad), packed bf16 k-pairs
#define WIMG 8704
__device__ __align__(16) uint32_t g_Wb[2][WIMG];  // W^T  hi/lo
__device__ __align__(16) uint32_t g_Fb[2][WIMG];  // ffw^T hi/lo

// ---------------- bf16 split helpers ------------------------------------------
__device__ __forceinline__ uint32_t pack_hi(float a, float b) {
    return (uint32_t)__bfloat16_as_ushort(__float2bfloat16(a)) |
           ((uint32_t)__bfloat16_as_ushort(__float2bfloat16(b)) << 16);
}
__device__ __forceinline__ uint32_t pack_lo(float a, float b) {
    float ra = a - __bfloat162float(__float2bfloat16(a));
    float rb = b - __bfloat162float(__float2bfloat16(b));
    return pack_hi(ra, rb);
}

// m16n8k16 bf16 MMA, fp32 accumulate in place
__device__ __forceinline__ void mma16816(float* c, uint32_t a0, uint32_t a1,
                                         uint32_t a2, uint32_t a3,
                                         uint32_t b0, uint32_t b1) {
    asm volatile("mma.sync.aligned.m16n8k16.row.col.f32.bf16.bf16.f32 "
                 "{%0,%1,%2,%3}, {%4,%5,%6,%7}, {%8,%9}, {%0,%1,%2,%3};"
                 : "+f"(c[0]), "+f"(c[1]), "+f"(c[2]), "+f"(c[3])
                 : "r"(a0), "r"(a1), "r"(a2), "r"(a3), "r"(b0), "r"(b1));
}

// ---------------- kernel P: pre-split weights into SMEM-image layout ----------
// image[n*68 + c] = packed bf16 of (W[2c][n], W[2c+1][n]); cols 64..67 = pad
__global__ void precompute_kernel(const float* __restrict__ W,
                                  const float* __restrict__ ffw) {
    const int t = threadIdx.x;
    for (int p = t; p < WIMG; p += 256) {
        int n = p / 68, c = p % 68;
        if (c < 64) {
            int k0 = c * 2;
            float w0 = W[k0 * 128 + n],   w1 = W[(k0 + 1) * 128 + n];
            float f0 = ffw[k0 * 128 + n], f1 = ffw[(k0 + 1) * 128 + n];
            g_Wb[0][p] = pack_hi(w0, w1);  g_Wb[1][p] = pack_lo(w0, w1);
            g_Fb[0][p] = pack_hi(f0, f1);  g_Fb[1][p] = pack_lo(f0, f1);
        } else {
            g_Wb[0][p] = 0; g_Wb[1][p] = 0; g_Fb[0][p] = 0; g_Fb[1][p] = 0;
        }
    }
}

// ---------------- shared tensor-GEMM core --------------------------------------
// Block: 256 threads (8 warps), M-tile = 128 rows, N=128, K=128.
// Warp w owns rows [w*16, w*16+16). acc[nt][4] = m16n8 D fragment, nt = 0..15.
// SMEM: A_hi/A_lo/B_hi/B_lo as [128][68] u32 images (conflict-free: stride 68
// => bank = (4*group + tid) mod 32, bijective over the warp's quad pattern).
#define AHI_OFF 0
#define ALO_OFF 34816
#define BHI_OFF 69632
#define BLO_OFF 104448
#define AUX_OFF 139264
#define GT_SMEM (139264 + 1024)

__device__ __forceinline__ void gemm_core(char* smem,
                                          const float* __restrict__ in,
                                          const uint32_t* __restrict__ bhi,
                                          const uint32_t* __restrict__ blo,
                                          int tile0, float acc[16][4]) {
    const int t = threadIdx.x;

    // stage B (verbatim uint4 copy of pre-built images: 2176 uint4 each)
    for (int i = t; i < WIMG / 4; i += 256) {
        ((uint4*)(smem + BHI_OFF))[i] = ((const uint4*)bhi)[i];
        ((uint4*)(smem + BLO_OFF))[i] = ((const uint4*)blo)[i];
    }
    // stage A: split fp32 rows into bf16 hi/lo packed k-pairs
    uint32_t* Ah = (uint32_t*)(smem + AHI_OFF);
    uint32_t* Al = (uint32_t*)(smem + ALO_OFF);
    for (int i = t; i < 128 * 64; i += 256) {
        int row = i >> 6, c = i & 63;
        int gm = tile0 + row;
        float2 xv = make_float2(0.f, 0.f);
        if (gm < N_NODES) xv = *(const float2*)&in[(size_t)gm * 128 + c * 2];
        Ah[row * 68 + c] = pack_hi(xv.x, xv.y);
        Al[row * 68 + c] = pack_lo(xv.x, xv.y);
    }
    __syncthreads();

    const int lane = t & 31, warp = t >> 5;
    const int g = lane >> 2, q = lane & 3;
    const uint32_t* Bh = (const uint32_t*)(smem + BHI_OFF);
    const uint32_t* Bl = (const uint32_t*)(smem + BLO_OFF);
    const int rb = warp * 16;

    #pragma unroll
    for (int nt = 0; nt < 16; nt++)
        acc[nt][0] = acc[nt][1] = acc[nt][2] = acc[nt][3] = 0.f;

    for (int ks = 0; ks < 8; ks++) {
        const int ab = (rb + g) * 68 + ks * 8 + q;
        const uint32_t ah0 = Ah[ab],           ah1 = Ah[ab + 8 * 68];
        const uint32_t ah2 = Ah[ab + 4],       ah3 = Ah[ab + 8 * 68 + 4];
        const uint32_t al0 = Al[ab],           al1 = Al[ab + 8 * 68];
        const uint32_t al2 = Al[ab + 4],       al3 = Al[ab + 8 * 68 + 4];
        #pragma unroll
        for (int nt = 0; nt < 16; nt++) {
            const int bb = (nt * 8 + g) * 68 + ks * 8 + q;
            const uint32_t bh0 = Bh[bb], bh1 = Bh[bb + 4];
            const uint32_t bl0 = Bl[bb], bl1 = Bl[bb + 4];
            mma16816(acc[nt], ah0, ah1, ah2, ah3, bh0, bh1);  // Ahi*Bhi
            mma16816(acc[nt], ah0, ah1, ah2, ah3, bl0, bl1);  // Ahi*Blo
            mma16816(acc[nt], al0, al1, al2, al3, bh0, bh1);  // Alo*Bhi
        }
    }
}

// ---------------- kernel 1: h = x@W (tensor) + a_s/a_d -------------------------
__global__ void __launch_bounds__(256, 1)
gemm1_tc_kernel(const float* __restrict__ x,
                const float* __restrict__ att_src,
                const float* __restrict__ att_dst) {
    extern __shared__ char smem[];
    const int t = threadIdx.x;
    const int tile0 = blockIdx.x * 128;
    if (t < 128) {
        ((float*)(smem + AUX_OFF))[t]       = att_src[t];
        ((float*)(smem + AUX_OFF + 512))[t] = att_dst[t];
    }
    float acc[16][4];
    gemm_core(smem, x, g_Wb[0], g_Wb[1], tile0, acc);

    const float* as_s = (const float*)(smem + AUX_OFF);
    const float* ad_s = (const float*)(smem + AUX_OFF + 512);
    const int lane = t & 31, warp = t >> 5;
    const int g = lane >> 2, q = lane & 3;
    const int r0 = tile0 + warp * 16 + g, r1 = r0 + 8;

    float as0[8], ad0[8], as1[8], ad1[8];
    #pragma unroll
    for (int h = 0; h < 8; h++) { as0[h]=ad0[h]=as1[h]=ad1[h]=0.f; }

    #pragma unroll
    for (int nt = 0; nt < 16; nt++) {
        const int c = nt * 8 + q * 2;
        const int h = nt >> 1;
        as0[h] += acc[nt][0] * as_s[c] + acc[nt][1] * as_s[c + 1];
        ad0[h] += acc[nt][0] * ad_s[c] + acc[nt][1] * ad_s[c + 1];
        as1[h] += acc[nt][2] * as_s[c] + acc[nt][3] * as_s[c + 1];
        ad1[h] += acc[nt][2] * ad_s[c] + acc[nt][3] * ad_s[c + 1];
        if (r0 < N_NODES)
            *(float2*)&g_h[(size_t)r0 * 128 + c] = make_float2(acc[nt][0], acc[nt][1]);
        if (r1 < N_NODES)
            *(float2*)&g_h[(size_t)r1 * 128 + c] = make_float2(acc[nt][2], acc[nt][3]);
    }
    // quad reduction (lanes q=0..3 share rows r0/r1)
    #pragma unroll
    for (int h = 0; h < 8; h++) {
        #pragma unroll
        for (int o = 1; o < 4; o <<= 1) {
            as0[h] += __shfl_xor_sync(0xFFFFFFFFu, as0[h], o);
            ad0[h] += __shfl_xor_sync(0xFFFFFFFFu, ad0[h], o);
            as1[h] += __shfl_xor_sync(0xFFFFFFFFu, as1[h], o);
            ad1[h] += __shfl_xor_sync(0xFFFFFFFFu, ad1[h], o);
        }
    }
    if (q == 0) {
        if (r0 < N_NODES) {
            #pragma unroll
            for (int h = 0; h < 8; h++) {
                g_as[(size_t)r0 * 8 + h] = as0[h];
                g_ad[(size_t)r0 * 8 + h] = ad0[h];
            }
        }
        if (r1 < N_NODES) {
            #pragma unroll
            for (int h = 0; h < 8; h++) {
                g_as[(size_t)r1 * 8 + h] = as1[h];
                g_ad[(size_t)r1 * 8 + h] = ad1[h];
            }
        }
    }
}

// ---------------- kernel 6: out = x + (v @ ffw) + ffb (tensor) ------------------
__global__ void __launch_bounds__(256, 1)
gemm2_tc_kernel(const float* __restrict__ x,
                const float* __restrict__ ffb,
                float* __restrict__ out) {
    extern __shared__ char smem[];
    const int t = threadIdx.x;
    const int tile0 = blockIdx.x * 128;
    if (t < 128) ((float*)(smem + AUX_OFF))[t] = ffb[t];

    float acc[16][4];
    gemm_core(smem, g_v, g_Fb[0], g_Fb[1], tile0, acc);

    const float* fb = (const float*)(smem + AUX_OFF);
    const int lane = t & 31, warp = t >> 5;
    const int g = lane >> 2, q = lane & 3;
    const int r0 = tile0 + warp * 16 + g, r1 = r0 + 8;

    #pragma unroll
    for (int nt = 0; nt < 16; nt++) {
        const int c = nt * 8 + q * 2;
        if (r0 < N_NODES) {
            float2 xr = *(const float2*)&x[(size_t)r0 * 128 + c];
            *(float2*)&out[(size_t)r0 * 128 + c] =
                make_float2(xr.x + acc[nt][0] + fb[c], xr.y + acc[nt][1] + fb[c + 1]);
        }
        if (r1 < N_NODES) {
            float2 xr = *(const float2*)&x[(size_t)r1 * 128 + c];
            *(float2*)&out[(size_t)r1 * 128 + c] =
                make_float2(xr.x + acc[nt][2] + fb[c], xr.y + acc[nt][3] + fb[c + 1]);
        }
    }
}

// ---------------- kernel 2: degree histogram ----------------------------------
__global__ void hist_kernel(const int* __restrict__ ei) {
    int i = blockIdx.x * blockDim.x + threadIdx.x;
    if (i >= ET) return;
    int d = (i < N_EDGES) ? ei[N_EDGES + i] : (i - N_EDGES);
    atomicAdd(&g_deg[d], 1);
}

// ---------------- kernel 3: single-pass decoupled-lookback exclusive scan -----
__device__ __forceinline__ int warp_incl_scan(int v, int lane) {
    #pragma unroll
    for (int o = 1; o < 32; o <<= 1) {
        int u = __shfl_up_sync(0xFFFFFFFFu, v, o);
        if (lane >= o) v += u;
    }
    return v;
}

__global__ void scan_kernel() {
    __shared__ int wsum[8];
    __shared__ int base_sh;
    const int t = threadIdx.x, lane = t & 31, w = t >> 5;
    const int b = blockIdx.x;
    const int i = b * 256 + t;
    const int v = (i < N_NODES) ? g_deg[i] : 0;
    int s = warp_incl_scan(v, lane);
    if (lane == 31) wsum[w] = s;
    __syncthreads();
    if (t < 8) {
        int ws = wsum[t];
        #pragma unroll
        for (int o = 1; o < 8; o <<= 1) {
            int u = __shfl_up_sync(0xFFu, ws, o);
            if (t >= o) ws += u;
        }
        wsum[t] = ws;
    }
    __syncthreads();
    const int incl = ((w > 0) ? wsum[w - 1] : 0) + s;

    if (t == 255) atomicExch(&g_bsum[b], incl + 1);

    if (w == 0) {
        int sum = 0;
        for (int p = b - 1 - lane; p >= 0; p -= 32) {
            int val;
            do { val = atomicAdd(&g_bsum[p], 0); } while (val == 0);
            sum += val - 1;
        }
        #pragma unroll
        for (int o = 16; o > 0; o >>= 1) sum += __shfl_xor_sync(0xFFFFFFFFu, sum, o);
        if (lane == 0) base_sh = sum;
    }
    __syncthreads();

    if (i < N_NODES) {
        const int off = base_sh + incl - v;
        g_off[i] = off;
        g_cur[i] = off;
    }
}

// ---------------- kernel 4: CSR fill (payload = source node id) ---------------
__global__ void csr_fill_kernel(const int* __restrict__ ei) {
    int i = blockIdx.x * blockDim.x + threadIdx.x;
    if (i >= ET) return;
    int s, d;
    if (i < N_EDGES) { s = ei[i]; d = ei[N_EDGES + i]; }
    else             { s = d = i - N_EDGES; }
    int pos = atomicAdd(&g_cur[d], 1);
    g_src[pos] = s;
}

// ---------------- kernel 5: gather + softmax + bias + LayerNorm -> g_v --------
__global__ void gather_ln_kernel(const float* __restrict__ conv_bias,
                                 const float* __restrict__ ln_g,
                                 const float* __restrict__ ln_b) {
    int wid  = (blockIdx.x * blockDim.x + threadIdx.x) >> 5;
    int lane = threadIdx.x & 31;
    if (wid >= N_NODES) return;
    const int n  = wid;
    const int hd = lane >> 2;
    const int start = g_off[n];
    const int end   = start + g_deg[n];
    const float ad  = g_ad[(size_t)n * NHEAD + hd];

    float wsum = 0.f;
    float ax = 0.f, ay = 0.f, az = 0.f, aw = 0.f;

    int e = start;
    for (; e + 4 <= end; e += 4) {
        const int s0 = g_src[e],   s1 = g_src[e+1];
        const int s2 = g_src[e+2], s3 = g_src[e+3];
        float l0 = g_as[(size_t)s0 * NHEAD + hd] + ad;
        float l1 = g_as[(size_t)s1 * NHEAD + hd] + ad;
        float l2 = g_as[(size_t)s2 * NHEAD + hd] + ad;
        float l3 = g_as[(size_t)s3 * NHEAD + hd] + ad;
        float4 h0 = *(const float4*)&g_h[(size_t)s0 * HC + lane * 4];
        float4 h1 = *(const float4*)&g_h[(size_t)s1 * HC + lane * 4];
        float4 h2 = *(const float4*)&g_h[(size_t)s2 * HC + lane * 4];
        float4 h3 = *(const float4*)&g_h[(size_t)s3 * HC + lane * 4];
        l0 = l0 > 0.f ? l0 : NEG_SLOPE * l0;
        l1 = l1 > 0.f ? l1 : NEG_SLOPE * l1;
        l2 = l2 > 0.f ? l2 : NEG_SLOPE * l2;
        l3 = l3 > 0.f ? l3 : NEG_SLOPE * l3;
        const float w0 = __expf(l0), w1 = __expf(l1);
        const float w2 = __expf(l2), w3 = __expf(l3);
        wsum += (w0 + w1) + (w2 + w3);
        ax += w0*h0.x + w1*h1.x + w2*h2.x + w3*h3.x;
        ay += w0*h0.y + w1*h1.y + w2*h2.y + w3*h3.y;
        az += w0*h0.z + w1*h1.z + w2*h2.z + w3*h3.z;
        aw += w0*h0.w + w1*h1.w + w2*h2.w + w3*h3.w;
    }
    for (; e < end; e++) {
        const int s = g_src[e];
        float lg = g_as[(size_t)s * NHEAD + hd] + ad;
        lg = lg > 0.f ? lg : NEG_SLOPE * lg;
        const float ww = __expf(lg);
        wsum += ww;
        float4 hv = *(const float4*)&g_h[(size_t)s * HC + lane * 4];
        ax += ww * hv.x; ay += ww * hv.y;
        az += ww * hv.z; aw += ww * hv.w;
    }

    const float dinv = 1.0f / wsum;
    float4 cb = *(const float4*)&conv_bias[lane * 4];
    float4 v  = make_float4(ax * dinv + cb.x, ay * dinv + cb.y,
                            az * dinv + cb.z, aw * dinv + cb.w);

    float s = v.x + v.y + v.z + v.w;
    #pragma unroll
    for (int o = 16; o > 0; o >>= 1) s += __shfl_xor_sync(0xFFFFFFFFu, s, o);
    const float mu = s * (1.0f / 128.0f);

    float dx = v.x - mu, dy = v.y - mu, dz = v.z - mu, dw = v.w - mu;
    float sq = dx*dx + dy*dy + dz*dz + dw*dw;
    #pragma unroll
    for (int o = 16; o > 0; o >>= 1) sq += __shfl_xor_sync(0xFFFFFFFFu, sq, o);
    const float rstd = rsqrtf(sq * (1.0f / 128.0f) + LN_EPS);

    float4 gg = *(const float4*)&ln_g[lane * 4];
    float4 bb = *(const float4*)&ln_b[lane * 4];
    *(float4*)&g_v[(size_t)n * HC + lane * 4] =
        make_float4(dx*rstd*gg.x + bb.x, dy*rstd*gg.y + bb.y,
                    dz*rstd*gg.z + bb.z, dw*rstd*gg.w + bb.w);
}

// ---------------- launch -------------------------------------------------------
extern "C" void kernel_launch(void* const* d_in, const int* in_sizes, int n_in,
                              void* d_out, int out_size) {
    const float* x        = (const float*)d_in[0];
    const int*   ei       = (const int*)  d_in[1];
    const float* W        = (const float*)d_in[2];
    const float* att_src  = (const float*)d_in[3];
    const float* att_dst  = (const float*)d_in[4];
    const float* conv_b   = (const float*)d_in[5];
    const float* ln_g     = (const float*)d_in[6];
    const float* ln_b     = (const float*)d_in[7];
    const float* ffw      = (const float*)d_in[8];
    const float* ffb      = (const float*)d_in[9];
    float*       out      = (float*)d_out;

    cudaFuncSetAttribute(gemm1_tc_kernel, cudaFuncAttributeMaxDynamicSharedMemorySize, GT_SMEM);
    cudaFuncSetAttribute(gemm2_tc_kernel, cudaFuncAttributeMaxDynamicSharedMemorySize, GT_SMEM);

    const int EB = (ET + 255) / 256;           // 3321
    const int WB = (N_NODES * 32 + 255) / 256; // 6250 (warp per node)

    void* deg_ptr = nullptr;  cudaGetSymbolAddress(&deg_ptr,  g_deg);
    void* bsum_ptr = nullptr; cudaGetSymbolAddress(&bsum_ptr, g_bsum);
    cudaMemsetAsync(deg_ptr,  0, (size_t)N_NODES * sizeof(int));   // launch 1
    cudaMemsetAsync(bsum_ptr, 0, 256 * sizeof(int));               // launch 2

    precompute_kernel<<<1, 256>>>(W, ffw);                         // launch 3
    hist_kernel      <<<EB, 256>>>(ei);                            // launch 4
    scan_kernel      <<<NB, 256>>>();                              // launch 5
    gemm1_tc_kernel  <<<GEMM_BLOCKS, 256, GT_SMEM>>>(x, att_src, att_dst); // launch 6 (profiled)
    csr_fill_kernel  <<<EB, 256>>>(ei);                            // launch 7
    gather_ln_kernel <<<WB, 256>>>(conv_b, ln_g, ln_b);            // launch 8
    gemm2_tc_kernel  <<<GEMM_BLOCKS, 256, GT_SMEM>>>(x, ffb, out); // launch 9
}